// round 2
// baseline (speedup 1.0000x reference)
#include <cuda_runtime.h>

// Problem constants (fixed by the dataset problem)
#define NNODES 100000
#define NEDGES 3200000
#define INDIM  128
#define HID    64
#define NGRAPH 256

// ---------------- scratch (device globals; no allocations allowed) ---------
__device__ float g_dis[NNODES];                    // deg, then rsqrt(deg)
__device__ int   g_row[NEDGES];
__device__ int   g_col[NEDGES];
__device__ float g_norm[NEDGES];
__device__ float g_bufA[(size_t)NNODES * HID];     // xl (layer input after GEMM)
__device__ float g_bufB[(size_t)NNODES * HID];     // h1
__device__ float g_bufC[(size_t)NNODES * HID];     // h2
__device__ int   g_i64;                            // 1 if indices are int64

// ---------------- helpers --------------------------------------------------
__device__ __forceinline__ long long load_idx(const void* p, long long i, int i64) {
    return i64 ? ((const long long*)p)[i] : (long long)((const int*)p)[i];
}

__device__ __forceinline__ void red_add_v4(float* addr, float a, float b, float c, float d) {
    asm volatile("red.global.add.v4.f32 [%0], {%1, %2, %3, %4};"
                 :: "l"(addr), "f"(a), "f"(b), "f"(c), "f"(d) : "memory");
}

// ---------------- kernels --------------------------------------------------

// Detect int64 vs int32 index layout. If data is int32, reading pairs as
// int64 yields values >= 2^32 (hi word is the next random index, nonzero
// with prob 1 - 1e-5 per sample; we check 16). Deterministic per input.
__global__ void k_detect(const void* ei) {
    if (threadIdx.x == 0 && blockIdx.x == 0) {
        const long long* p = (const long long*)ei;
        int ok64 = 1;
        for (int i = 0; i < 16; i++) {
            long long v = p[i];
            if (v < 0 || v >= NNODES) { ok64 = 0; break; }
        }
        g_i64 = ok64;
    }
}

__global__ void k_deg_init() {
    int i = blockIdx.x * blockDim.x + threadIdx.x;
    if (i < NNODES) g_dis[i] = 1.0f;   // self-loop weight 1
}

__global__ void k_deg_acc(const void* __restrict__ ei, const float* __restrict__ ew) {
    int e = blockIdx.x * blockDim.x + threadIdx.x;
    if (e < NEDGES) {
        int i64 = g_i64;
        int c = (int)load_idx(ei, (long long)NEDGES + e, i64);
        atomicAdd(&g_dis[c], ew[e]);
    }
}

__global__ void k_rsqrt() {
    int i = blockIdx.x * blockDim.x + threadIdx.x;
    if (i < NNODES) g_dis[i] = rsqrtf(g_dis[i]);   // deg >= 1 always
}

__global__ void k_edgeprep(const void* __restrict__ ei, const float* __restrict__ ew) {
    int e = blockIdx.x * blockDim.x + threadIdx.x;
    if (e < NEDGES) {
        int i64 = g_i64;
        int r = (int)load_idx(ei, e, i64);
        int c = (int)load_idx(ei, (long long)NEDGES + e, i64);
        g_row[e]  = r;
        g_col[e]  = c;
        g_norm[e] = g_dis[r] * ew[e] * g_dis[c];
    }
}

// GEMM1: bufA = x @ W1 ; bufB = b1 + dis^2 * bufA  (self-loop folded in)
__global__ void k_gemm1(const float* __restrict__ x, const float* __restrict__ W1,
                        const float* __restrict__ b1) {
    __shared__ float Ws[INDIM * HID];
    for (int t = threadIdx.x; t < INDIM * HID; t += blockDim.x) Ws[t] = W1[t];
    __syncthreads();
    int j   = threadIdx.x & 63;
    int sub = threadIdx.x >> 6;          // 0..3
    int i   = blockIdx.x * 4 + sub;
    if (i >= NNODES) return;
    const float* xr = x + (size_t)i * INDIM;
    float acc = 0.f;
#pragma unroll 16
    for (int k = 0; k < INDIM; k++) acc = fmaf(xr[k], Ws[k * HID + j], acc);
    float d = g_dis[i];
    g_bufA[(size_t)i * HID + j] = acc;
    g_bufB[(size_t)i * HID + j] = b1[j] + d * d * acc;
}

// GEMM2: bufA = relu(bufB) @ W2 ; bufC = b2 + dis^2 * bufA
__global__ void k_gemm2(const float* __restrict__ W2, const float* __restrict__ b2) {
    __shared__ float Ws[HID * HID];
    for (int t = threadIdx.x; t < HID * HID; t += blockDim.x) Ws[t] = W2[t];
    __syncthreads();
    int j   = threadIdx.x & 63;
    int sub = threadIdx.x >> 6;
    int i   = blockIdx.x * 4 + sub;
    if (i >= NNODES) return;
    const float* hr = g_bufB + (size_t)i * HID;
    float acc = 0.f;
#pragma unroll 16
    for (int k = 0; k < HID; k++) acc = fmaf(fmaxf(hr[k], 0.f), Ws[k * HID + j], acc);
    float d = g_dis[i];
    g_bufA[(size_t)i * HID + j] = acc;
    g_bufC[(size_t)i * HID + j] = b2[j] + d * d * acc;
}

// Scatter: dst[col[e]] += norm[e] * bufA[row[e]]  (16 threads/edge, float4 + red.v4)
__global__ void k_scatter(int layer) {
    unsigned int gid = blockIdx.x * blockDim.x + threadIdx.x;
    unsigned int e = gid >> 4;
    if (e >= NEDGES) return;
    int q = (int)(gid & 15u) << 2;
    int r = g_row[e], c = g_col[e];
    float nm = g_norm[e];
    const float* src = g_bufA;
    float* dst = layer ? g_bufC : g_bufB;
    float4 v = *reinterpret_cast<const float4*>(src + (size_t)r * HID + q);
    red_add_v4(dst + (size_t)c * HID + q, v.x * nm, v.y * nm, v.z * nm, v.w * nm);
}

// Pool + head: per-graph block, binary search on sorted batch, no atomics.
__global__ void k_pool(const void* __restrict__ batch, const float* __restrict__ Wc,
                       const float* __restrict__ bc, float* __restrict__ out) {
    int g = blockIdx.x;
    int i64 = g_i64;
    // lower_bound(batch, g) and lower_bound(batch, g+1)
    int lo = 0, hi = NNODES;
    while (lo < hi) { int m = (lo + hi) >> 1; if (load_idx(batch, m, i64) < (long long)g) lo = m + 1; else hi = m; }
    int start = lo;
    hi = NNODES;
    while (lo < hi) { int m = (lo + hi) >> 1; if (load_idx(batch, m, i64) < (long long)g + 1) lo = m + 1; else hi = m; }
    int end = lo;

    __shared__ float partial[256];
    int j = threadIdx.x & 63;
    int sub = threadIdx.x >> 6;
    float acc = 0.f;
    for (int i = start + sub; i < end; i += 4)
        acc += fmaxf(g_bufC[(size_t)i * HID + j], 0.f);
    partial[threadIdx.x] = acc;
    __syncthreads();
    if (sub == 0) {
        float s = partial[j] + partial[j + 64] + partial[j + 128] + partial[j + 192];
        float cnt = (float)(end - start);
        float pooled = s / fmaxf(cnt, 1.0f);
        partial[j] = pooled * Wc[j];
    }
    __syncthreads();
    for (int off = 32; off > 0; off >>= 1) {
        if (threadIdx.x < off) partial[threadIdx.x] += partial[threadIdx.x + off];
        __syncthreads();
    }
    if (threadIdx.x == 0) out[g] = partial[0] + bc[0];
}

// ---------------- launch ---------------------------------------------------
extern "C" void kernel_launch(void* const* d_in, const int* in_sizes, int n_in,
                              void* d_out, int out_size) {
    const float* x      = (const float*)d_in[0];
    const void*  ei     = d_in[1];                 // int64 or int32, detected
    const float* ew     = (const float*)d_in[2];
    const void*  batch  = d_in[3];
    const float* W1     = (const float*)d_in[4];
    const float* b1     = (const float*)d_in[5];
    const float* W2     = (const float*)d_in[6];
    const float* b2     = (const float*)d_in[7];
    const float* Wc     = (const float*)d_in[8];
    const float* bc     = (const float*)d_in[9];
    float* out          = (float*)d_out;

    k_detect<<<1, 32>>>(ei);
    k_deg_init<<<(NNODES + 255) / 256, 256>>>();
    k_deg_acc<<<(NEDGES + 255) / 256, 256>>>(ei, ew);
    k_rsqrt<<<(NNODES + 255) / 256, 256>>>();
    k_edgeprep<<<(NEDGES + 255) / 256, 256>>>(ei, ew);

    k_gemm1<<<(NNODES + 3) / 4, 256>>>(x, W1, b1);
    {
        unsigned int total = (unsigned int)NEDGES * 16u;
        k_scatter<<<(total + 255) / 256, 256>>>(0);
    }
    k_gemm2<<<(NNODES + 3) / 4, 256>>>(W2, b2);
    {
        unsigned int total = (unsigned int)NEDGES * 16u;
        k_scatter<<<(total + 255) / 256, 256>>>(1);
    }
    k_pool<<<NGRAPH, 256>>>(batch, Wc, bc, out);
}

// round 6
// speedup vs baseline: 1.2718x; 1.2718x over previous
#include <cuda_runtime.h>

#define NNODES 100000
#define NEDGES 3200000
#define INDIM  128
#define HID    64
#define NGRAPH 256
#define NB     ((NNODES + 255) / 256)   // 391

// ---------------- scratch (device globals) ---------------------------------
__device__ float g_dis[NNODES];                    // deg -> rsqrt(deg)
__device__ int   g_cnt[NNODES];                    // in-degree (no self loop)
__device__ int   g_off[NNODES + 1];                // CSR offsets
__device__ int   g_cursor[NNODES];                 // fill cursors
__device__ int   g_bsum[NB];                       // block sums for scan
__device__ int   g_row[NEDGES];
__device__ int   g_col[NEDGES];
__device__ int   g_csr_src[NEDGES];                // CSR: source node per slot
__device__ float g_csr_nrm[NEDGES];                // CSR: norm per slot
__device__ float g_bufA[(size_t)NNODES * HID];     // xl (post-GEMM)
__device__ float g_bufB[(size_t)NNODES * HID];     // h (post-conv, relu'd)
__device__ int   g_i64;

// ---------------- helpers --------------------------------------------------
__device__ __forceinline__ long long load_idx(const void* p, long long i, int i64) {
    return i64 ? ((const long long*)p)[i] : (long long)((const int*)p)[i];
}

// ---------------- kernels --------------------------------------------------

// Launch 0: dtype detect + scratch init + GEMM1 (bufA = x @ W1), all fused.
__global__ void k_init_gemm1(const void* __restrict__ ei, const float* __restrict__ x,
                             const float* __restrict__ W1) {
    int gid = blockIdx.x * blockDim.x + threadIdx.x;
    if (gid < NNODES) { g_dis[gid] = 1.0f; g_cnt[gid] = 0; }   // self-loop weight 1
    if (gid == 0) {
        const long long* p = (const long long*)ei;
        int ok64 = 1;
        for (int i = 0; i < 16; i++) {
            long long v = p[i];
            if (v < 0 || v >= NNODES) { ok64 = 0; break; }
        }
        g_i64 = ok64;
    }
    __shared__ float Ws[INDIM * HID];
    for (int t = threadIdx.x; t < INDIM * HID; t += blockDim.x) Ws[t] = W1[t];
    __syncthreads();
    int j   = threadIdx.x & 63;
    int sub = threadIdx.x >> 6;
    int i   = blockIdx.x * 4 + sub;
    if (i >= NNODES) return;
    const float* xr = x + (size_t)i * INDIM;
    float acc = 0.f;
#pragma unroll 16
    for (int k = 0; k < INDIM; k++) acc = fmaf(xr[k], Ws[k * HID + j], acc);
    g_bufA[(size_t)i * HID + j] = acc;
}

// Launch 1: decode indices, count in-degree, accumulate weighted degree.
__global__ void k_pass1(const void* __restrict__ ei, const float* __restrict__ ew) {
    int e = blockIdx.x * blockDim.x + threadIdx.x;
    if (e >= NEDGES) return;
    int i64 = g_i64;
    int r = (int)load_idx(ei, e, i64);
    int c = (int)load_idx(ei, (long long)NEDGES + e, i64);
    g_row[e] = r;
    g_col[e] = c;
    atomicAdd(&g_dis[c], ew[e]);
    atomicAdd(&g_cnt[c], 1);
}

// Launch 2: dis = rsqrt(deg); per-block sums of cnt for the scan.
__global__ void k_rsqrt_bsum() {
    int i = blockIdx.x * blockDim.x + threadIdx.x;
    int v = 0;
    if (i < NNODES) { g_dis[i] = rsqrtf(g_dis[i]); v = g_cnt[i]; }
    __shared__ int sh[256];
    sh[threadIdx.x] = v;
    __syncthreads();
    for (int d = 128; d > 0; d >>= 1) {
        if (threadIdx.x < d) sh[threadIdx.x] += sh[threadIdx.x + d];
        __syncthreads();
    }
    if (threadIdx.x == 0) g_bsum[blockIdx.x] = sh[0];
}

// Launch 3: per-block: prefix over earlier blocks + in-block exclusive scan.
__global__ void k_scan() {
    __shared__ int red[256];
    __shared__ int sh[256];
    int tid = threadIdx.x;
    int b = blockIdx.x;
    // prefix = sum of g_bsum[j] for j < b
    int s = 0;
    for (int t = tid; t < NB; t += 256) if (t < b) s += g_bsum[t];
    red[tid] = s;
    __syncthreads();
    for (int d = 128; d > 0; d >>= 1) {
        if (tid < d) red[tid] += red[tid + d];
        __syncthreads();
    }
    int prefix = red[0];
    // in-block exclusive scan (Hillis-Steele inclusive, then subtract own)
    int i = b * 256 + tid;
    int v = (i < NNODES) ? g_cnt[i] : 0;
    sh[tid] = v;
    __syncthreads();
    for (int d = 1; d < 256; d <<= 1) {
        int t = (tid >= d) ? sh[tid - d] : 0;
        __syncthreads();
        sh[tid] += t;
        __syncthreads();
    }
    int excl = sh[tid] - v;
    if (i < NNODES) {
        int off = prefix + excl;
        g_off[i] = off;
        g_cursor[i] = off;
        if (i == NNODES - 1) g_off[NNODES] = off + v;   // == NEDGES
    }
}

// Launch 4: fill CSR slots with (source node, norm).
__global__ void k_fill(const float* __restrict__ ew) {
    int e = blockIdx.x * blockDim.x + threadIdx.x;
    if (e >= NEDGES) return;
    int r = g_row[e], c = g_col[e];
    float nm = g_dis[r] * ew[e] * g_dis[c];
    int pos = atomicAdd(&g_cursor[c], 1);
    g_csr_src[pos] = r;
    g_csr_nrm[pos] = nm;
}

// Launches 5 & 7: conv = gather over in-edges + self-loop + bias, relu'd store.
// Reads g_bufA, writes g_bufB (device symbols referenced in device code ONLY).
// 16 threads per node (4 float columns each). Edge idx/norm broadcast via shfl.
__global__ void __launch_bounds__(256) k_gather(const float* __restrict__ bias) {
    int node = (blockIdx.x * blockDim.x + threadIdx.x) >> 4;   // exact: 6250 blocks
    int lane = threadIdx.x & 15;
    unsigned gmask = 0xFFFFu << (threadIdx.x & 16);            // own half-warp
    int q = lane << 2;
    const float* __restrict__ src = g_bufA;
    float* __restrict__ dst = g_bufB;
    int start = g_off[node], end = g_off[node + 1];
    float d = g_dis[node];
    float dd = d * d;
    float4 sv = *reinterpret_cast<const float4*>(src + ((size_t)node << 6) + q);
    float4 acc;
    acc.x = bias[q]     + dd * sv.x;
    acc.y = bias[q + 1] + dd * sv.y;
    acc.z = bias[q + 2] + dd * sv.z;
    acc.w = bias[q + 3] + dd * sv.w;

    int e = start;
    for (; e + 16 <= end; e += 16) {
        int   myIdx = g_csr_src[e + lane];
        float myNm  = g_csr_nrm[e + lane];
#pragma unroll
        for (int k = 0; k < 16; k++) {
            int   r  = __shfl_sync(gmask, myIdx, k, 16);
            float nm = __shfl_sync(gmask, myNm, k, 16);
            float4 v = *reinterpret_cast<const float4*>(src + ((size_t)r << 6) + q);
            acc.x = fmaf(nm, v.x, acc.x);
            acc.y = fmaf(nm, v.y, acc.y);
            acc.z = fmaf(nm, v.z, acc.z);
            acc.w = fmaf(nm, v.w, acc.w);
        }
    }
    int n = end - e;
    if (n > 0) {
        int   myIdx = (lane < n) ? g_csr_src[e + lane] : 0;
        float myNm  = (lane < n) ? g_csr_nrm[e + lane] : 0.f;
        for (int k = 0; k < n; k++) {
            int   r  = __shfl_sync(gmask, myIdx, k, 16);
            float nm = __shfl_sync(gmask, myNm, k, 16);
            float4 v = *reinterpret_cast<const float4*>(src + ((size_t)r << 6) + q);
            acc.x = fmaf(nm, v.x, acc.x);
            acc.y = fmaf(nm, v.y, acc.y);
            acc.z = fmaf(nm, v.z, acc.z);
            acc.w = fmaf(nm, v.w, acc.w);
        }
    }
    // relu + store
    acc.x = fmaxf(acc.x, 0.f); acc.y = fmaxf(acc.y, 0.f);
    acc.z = fmaxf(acc.z, 0.f); acc.w = fmaxf(acc.w, 0.f);
    *reinterpret_cast<float4*>(dst + ((size_t)node << 6) + q) = acc;
}

// Launch 6: bufA = bufB(relu'd h1) @ W2
__global__ void k_gemm2(const float* __restrict__ W2) {
    __shared__ float Ws[HID * HID];
    for (int t = threadIdx.x; t < HID * HID; t += blockDim.x) Ws[t] = W2[t];
    __syncthreads();
    int j   = threadIdx.x & 63;
    int sub = threadIdx.x >> 6;
    int i   = blockIdx.x * 4 + sub;
    if (i >= NNODES) return;
    const float* hr = g_bufB + (size_t)i * HID;
    float acc = 0.f;
#pragma unroll 16
    for (int k = 0; k < HID; k++) acc = fmaf(hr[k], Ws[k * HID + j], acc);
    g_bufA[(size_t)i * HID + j] = acc;
}

// Launch 8: mean-pool per graph (binary search on sorted batch) + head.
__global__ void k_pool(const void* __restrict__ batch, const float* __restrict__ Wc,
                       const float* __restrict__ bc, float* __restrict__ out) {
    int g = blockIdx.x;
    int i64 = g_i64;
    int lo = 0, hi = NNODES;
    while (lo < hi) { int m = (lo + hi) >> 1; if (load_idx(batch, m, i64) < (long long)g) lo = m + 1; else hi = m; }
    int start = lo;
    hi = NNODES;
    while (lo < hi) { int m = (lo + hi) >> 1; if (load_idx(batch, m, i64) < (long long)g + 1) lo = m + 1; else hi = m; }
    int end = lo;

    __shared__ float partial[256];
    int j = threadIdx.x & 63;
    int sub = threadIdx.x >> 6;
    float acc = 0.f;
    for (int i = start + sub; i < end; i += 4)
        acc += g_bufB[(size_t)i * HID + j];
    partial[threadIdx.x] = acc;
    __syncthreads();
    if (sub == 0) {
        float s = partial[j] + partial[j + 64] + partial[j + 128] + partial[j + 192];
        float cnt = (float)(end - start);
        partial[j] = (s / fmaxf(cnt, 1.0f)) * Wc[j];
    }
    __syncthreads();
    for (int off = 32; off > 0; off >>= 1) {
        if (threadIdx.x < off) partial[threadIdx.x] += partial[threadIdx.x + off];
        __syncthreads();
    }
    if (threadIdx.x == 0) out[g] = partial[0] + bc[0];
}

// ---------------- launch ---------------------------------------------------
extern "C" void kernel_launch(void* const* d_in, const int* in_sizes, int n_in,
                              void* d_out, int out_size) {
    const float* x     = (const float*)d_in[0];
    const void*  ei    = d_in[1];
    const float* ew    = (const float*)d_in[2];
    const void*  batch = d_in[3];
    const float* W1    = (const float*)d_in[4];
    const float* b1    = (const float*)d_in[5];
    const float* W2    = (const float*)d_in[6];
    const float* b2    = (const float*)d_in[7];
    const float* Wc    = (const float*)d_in[8];
    const float* bc    = (const float*)d_in[9];
    float* out         = (float*)d_out;

    k_init_gemm1<<<(NNODES + 3) / 4, 256>>>(ei, x, W1);          // launch 0
    k_pass1<<<(NEDGES + 255) / 256, 256>>>(ei, ew);              // launch 1
    k_rsqrt_bsum<<<NB, 256>>>();                                 // launch 2
    k_scan<<<NB, 256>>>();                                       // launch 3
    k_fill<<<(NEDGES + 255) / 256, 256>>>(ew);                   // launch 4
    k_gather<<<(NNODES * 16) / 256, 256>>>(b1);                  // launch 5 (ncu slot)
    k_gemm2<<<(NNODES + 3) / 4, 256>>>(W2);                      // launch 6
    k_gather<<<(NNODES * 16) / 256, 256>>>(b2);                  // launch 7
    k_pool<<<NGRAPH, 256>>>(batch, Wc, bc, out);                 // launch 8
}

// round 8
// speedup vs baseline: 2.5906x; 2.0370x over previous
#include <cuda_runtime.h>
#include <cuda_fp16.h>

#define NNODES 100000
#define NEDGES 3200000
#define INDIM  128
#define HID    64
#define NGRAPH 256
#define NB     ((NNODES + 255) / 256)   // 391
#define NPB    32                       // nodes per gemm block (100000/32 = 3125 exact)

// ---------------- scratch (device globals) ---------------------------------
__device__ float  g_dis[NNODES];                    // deg -> rsqrt(deg)
__device__ int    g_cnt[NNODES];                    // in-degree (no self loop)
__device__ int    g_off[NNODES + 1];                // CSR offsets
__device__ int    g_cursor[NNODES];                 // fill cursors
__device__ int    g_bsum[NB];                       // block sums for scan
__device__ int2   g_edge[NEDGES];                   // packed {row, col}
__device__ int2   g_csr[NEDGES];                    // packed {src, norm-as-int}
__device__ float  g_bufA[(size_t)NNODES * HID];     // gemm out fp32
__device__ __half g_bufAh[(size_t)NNODES * HID];    // gemm out fp16 (gather source)
__device__ float  g_bufB[(size_t)NNODES * HID];     // conv out (relu'd), fp32
__device__ int    g_i64;

// ---------------- helpers --------------------------------------------------
__device__ __forceinline__ long long load_idx(const void* p, long long i, int i64) {
    return i64 ? ((const long long*)p)[i] : (long long)((const int*)p)[i];
}

// ---------------- kernels --------------------------------------------------

// Launch 0: dtype detect + scratch init + GEMM1 (bufA = x @ W1).
// 32 nodes/block, 8 accs/thread; x tile + W1 staged in smem once per block.
__global__ void __launch_bounds__(256) k_init_gemm1(const void* __restrict__ ei,
                                                    const float* __restrict__ x,
                                                    const float* __restrict__ W1) {
    int gid = blockIdx.x * blockDim.x + threadIdx.x;
    if (gid < NNODES) { g_dis[gid] = 1.0f; g_cnt[gid] = 0; }   // self-loop weight 1
    if (gid == 0) {
        const long long* p = (const long long*)ei;
        int ok64 = 1;
        for (int i = 0; i < 16; i++) {
            long long v = p[i];
            if (v < 0 || v >= NNODES) { ok64 = 0; break; }
        }
        g_i64 = ok64;
    }
    __shared__ float Ws[INDIM * HID];   // 32 KB, [k][j]
    __shared__ float Xs[NPB * INDIM];   // 16 KB
    for (int t = threadIdx.x; t < INDIM * HID; t += 256) Ws[t] = W1[t];
    {
        const float4* xin = (const float4*)(x + (size_t)blockIdx.x * NPB * INDIM);
        float4* xs4 = (float4*)Xs;
#pragma unroll
        for (int t = 0; t < NPB * INDIM / 4 / 256; t++)
            xs4[threadIdx.x + t * 256] = xin[threadIdx.x + t * 256];
    }
    __syncthreads();
    int j   = threadIdx.x & 63;
    int sub = threadIdx.x >> 6;          // 0..3, each handles 8 nodes
    float acc[8] = {0.f, 0.f, 0.f, 0.f, 0.f, 0.f, 0.f, 0.f};
    for (int k = 0; k < INDIM; k += 4) {
        float w0 = Ws[k * HID + j];
        float w1 = Ws[(k + 1) * HID + j];
        float w2 = Ws[(k + 2) * HID + j];
        float w3 = Ws[(k + 3) * HID + j];
#pragma unroll
        for (int t = 0; t < 8; t++) {
            float4 xv = *reinterpret_cast<const float4*>(&Xs[(sub * 8 + t) * INDIM + k]);
            acc[t] = fmaf(xv.x, w0, fmaf(xv.y, w1, fmaf(xv.z, w2, fmaf(xv.w, w3, acc[t]))));
        }
    }
    int base = blockIdx.x * NPB + sub * 8;
#pragma unroll
    for (int t = 0; t < 8; t++) {
        size_t o = (size_t)(base + t) * HID + j;
        g_bufA[o]  = acc[t];
        g_bufAh[o] = __float2half(acc[t]);
    }
}

// Launch 1: decode indices, count in-degree, accumulate weighted degree.
__global__ void k_pass1(const void* __restrict__ ei, const float* __restrict__ ew) {
    int e = blockIdx.x * blockDim.x + threadIdx.x;
    if (e >= NEDGES) return;
    int i64 = g_i64;
    int r = (int)load_idx(ei, e, i64);
    int c = (int)load_idx(ei, (long long)NEDGES + e, i64);
    g_edge[e] = make_int2(r, c);
    atomicAdd(&g_dis[c], ew[e]);
    atomicAdd(&g_cnt[c], 1);
}

// Launch 2: dis = rsqrt(deg); per-block sums of cnt for the scan.
__global__ void k_rsqrt_bsum() {
    int i = blockIdx.x * blockDim.x + threadIdx.x;
    int v = 0;
    if (i < NNODES) { g_dis[i] = rsqrtf(g_dis[i]); v = g_cnt[i]; }
    __shared__ int sh[256];
    sh[threadIdx.x] = v;
    __syncthreads();
    for (int d = 128; d > 0; d >>= 1) {
        if (threadIdx.x < d) sh[threadIdx.x] += sh[threadIdx.x + d];
        __syncthreads();
    }
    if (threadIdx.x == 0) g_bsum[blockIdx.x] = sh[0];
}

// Launch 3: per-block prefix over earlier blocks + in-block exclusive scan.
__global__ void k_scan() {
    __shared__ int red[256];
    __shared__ int sh[256];
    int tid = threadIdx.x;
    int b = blockIdx.x;
    int s = 0;
    for (int t = tid; t < NB; t += 256) if (t < b) s += g_bsum[t];
    red[tid] = s;
    __syncthreads();
    for (int d = 128; d > 0; d >>= 1) {
        if (tid < d) red[tid] += red[tid + d];
        __syncthreads();
    }
    int prefix = red[0];
    int i = b * 256 + tid;
    int v = (i < NNODES) ? g_cnt[i] : 0;
    sh[tid] = v;
    __syncthreads();
    for (int d = 1; d < 256; d <<= 1) {
        int t = (tid >= d) ? sh[tid - d] : 0;
        __syncthreads();
        sh[tid] += t;
        __syncthreads();
    }
    int excl = sh[tid] - v;
    if (i < NNODES) {
        int off = prefix + excl;
        g_off[i] = off;
        g_cursor[i] = off;
        if (i == NNODES - 1) g_off[NNODES] = off + v;   // == NEDGES
    }
}

// Launch 4: fill CSR slots with packed {src, norm}.
__global__ void k_fill(const float* __restrict__ ew) {
    int e = blockIdx.x * blockDim.x + threadIdx.x;
    if (e >= NEDGES) return;
    int2 rc = g_edge[e];
    float nm = g_dis[rc.x] * ew[e] * g_dis[rc.y];
    int pos = atomicAdd(&g_cursor[rc.y], 1);
    g_csr[pos] = make_int2(rc.x, __float_as_int(nm));
}

// Launches 5 & 7: conv = gather over in-edges (fp16 rows) + self-loop + bias.
// 16 threads/node, 4 columns each; neighbor rows read fp16 (128B = 1 line),
// self value from fp32 copy; fp32 accumulate; relu'd fp32 store to bufB.
__global__ void __launch_bounds__(256) k_gather(const float* __restrict__ bias) {
    int node = (blockIdx.x * blockDim.x + threadIdx.x) >> 4;   // exact: 6250 blocks
    int lane = threadIdx.x & 15;
    unsigned gmask = 0xFFFFu << (threadIdx.x & 16);            // own half-warp
    int q = lane << 2;                                          // column base
    const __half* __restrict__ srcH = g_bufAh;
    int start = g_off[node], end = g_off[node + 1];
    float d = g_dis[node];
    float dd = d * d;
    float4 sv = *reinterpret_cast<const float4*>(g_bufA + ((size_t)node << 6) + q);
    float4 acc;
    acc.x = bias[q]     + dd * sv.x;
    acc.y = bias[q + 1] + dd * sv.y;
    acc.z = bias[q + 2] + dd * sv.z;
    acc.w = bias[q + 3] + dd * sv.w;

    int e = start;
    for (; e + 16 <= end; e += 16) {
        int2 m = g_csr[e + lane];
#pragma unroll
        for (int k = 0; k < 16; k++) {
            int   r  = __shfl_sync(gmask, m.x, k, 16);
            float nm = __int_as_float(__shfl_sync(gmask, m.y, k, 16));
            uint2 raw = *reinterpret_cast<const uint2*>(srcH + ((size_t)r << 6) + q);
            float2 f01 = __half22float2(*reinterpret_cast<__half2*>(&raw.x));
            float2 f23 = __half22float2(*reinterpret_cast<__half2*>(&raw.y));
            acc.x = fmaf(nm, f01.x, acc.x);
            acc.y = fmaf(nm, f01.y, acc.y);
            acc.z = fmaf(nm, f23.x, acc.z);
            acc.w = fmaf(nm, f23.y, acc.w);
        }
    }
    int n = end - e;
    if (n > 0) {
        int2 m = (lane < n) ? g_csr[e + lane] : make_int2(0, 0);
        for (int k = 0; k < n; k++) {
            int   r  = __shfl_sync(gmask, m.x, k, 16);
            float nm = __int_as_float(__shfl_sync(gmask, m.y, k, 16));
            uint2 raw = *reinterpret_cast<const uint2*>(srcH + ((size_t)r << 6) + q);
            float2 f01 = __half22float2(*reinterpret_cast<__half2*>(&raw.x));
            float2 f23 = __half22float2(*reinterpret_cast<__half2*>(&raw.y));
            acc.x = fmaf(nm, f01.x, acc.x);
            acc.y = fmaf(nm, f01.y, acc.y);
            acc.z = fmaf(nm, f23.x, acc.z);
            acc.w = fmaf(nm, f23.y, acc.w);
        }
    }
    acc.x = fmaxf(acc.x, 0.f); acc.y = fmaxf(acc.y, 0.f);
    acc.z = fmaxf(acc.z, 0.f); acc.w = fmaxf(acc.w, 0.f);
    *reinterpret_cast<float4*>(g_bufB + ((size_t)node << 6) + q) = acc;
}

// Launch 6: bufA(+fp16 copy) = bufB(relu'd h1) @ W2. Same blocking as gemm1.
__global__ void __launch_bounds__(256) k_gemm2(const float* __restrict__ W2) {
    __shared__ float Ws[HID * HID];    // 16 KB
    __shared__ float Xs[NPB * HID];    // 8 KB
    for (int t = threadIdx.x; t < HID * HID; t += 256) Ws[t] = W2[t];
    {
        const float4* xin = (const float4*)(g_bufB + (size_t)blockIdx.x * NPB * HID);
        float4* xs4 = (float4*)Xs;
#pragma unroll
        for (int t = 0; t < NPB * HID / 4 / 256; t++)
            xs4[threadIdx.x + t * 256] = xin[threadIdx.x + t * 256];
    }
    __syncthreads();
    int j   = threadIdx.x & 63;
    int sub = threadIdx.x >> 6;
    float acc[8] = {0.f, 0.f, 0.f, 0.f, 0.f, 0.f, 0.f, 0.f};
    for (int k = 0; k < HID; k += 4) {
        float w0 = Ws[k * HID + j];
        float w1 = Ws[(k + 1) * HID + j];
        float w2 = Ws[(k + 2) * HID + j];
        float w3 = Ws[(k + 3) * HID + j];
#pragma unroll
        for (int t = 0; t < 8; t++) {
            float4 xv = *reinterpret_cast<const float4*>(&Xs[(sub * 8 + t) * HID + k]);
            acc[t] = fmaf(xv.x, w0, fmaf(xv.y, w1, fmaf(xv.z, w2, fmaf(xv.w, w3, acc[t]))));
        }
    }
    int base = blockIdx.x * NPB + sub * 8;
#pragma unroll
    for (int t = 0; t < 8; t++) {
        size_t o = (size_t)(base + t) * HID + j;
        g_bufA[o]  = acc[t];
        g_bufAh[o] = __float2half(acc[t]);
    }
}

// Launch 8: mean-pool per graph (binary search on sorted batch) + head.
__global__ void k_pool(const void* __restrict__ batch, const float* __restrict__ Wc,
                       const float* __restrict__ bc, float* __restrict__ out) {
    int g = blockIdx.x;
    int i64 = g_i64;
    int lo = 0, hi = NNODES;
    while (lo < hi) { int m = (lo + hi) >> 1; if (load_idx(batch, m, i64) < (long long)g) lo = m + 1; else hi = m; }
    int start = lo;
    hi = NNODES;
    while (lo < hi) { int m = (lo + hi) >> 1; if (load_idx(batch, m, i64) < (long long)g + 1) lo = m + 1; else hi = m; }
    int end = lo;

    __shared__ float partial[256];
    int j = threadIdx.x & 63;
    int sub = threadIdx.x >> 6;
    float acc = 0.f;
    for (int i = start + sub; i < end; i += 4)
        acc += g_bufB[(size_t)i * HID + j];
    partial[threadIdx.x] = acc;
    __syncthreads();
    if (sub == 0) {
        float s = partial[j] + partial[j + 64] + partial[j + 128] + partial[j + 192];
        float cnt = (float)(end - start);
        partial[j] = (s / fmaxf(cnt, 1.0f)) * Wc[j];
    }
    __syncthreads();
    for (int off = 32; off > 0; off >>= 1) {
        if (threadIdx.x < off) partial[threadIdx.x] += partial[threadIdx.x + off];
        __syncthreads();
    }
    if (threadIdx.x == 0) out[g] = partial[0] + bc[0];
}

// ---------------- launch ---------------------------------------------------
extern "C" void kernel_launch(void* const* d_in, const int* in_sizes, int n_in,
                              void* d_out, int out_size) {
    const float* x     = (const float*)d_in[0];
    const void*  ei    = d_in[1];
    const float* ew    = (const float*)d_in[2];
    const void*  batch = d_in[3];
    const float* W1    = (const float*)d_in[4];
    const float* b1    = (const float*)d_in[5];
    const float* W2    = (const float*)d_in[6];
    const float* b2    = (const float*)d_in[7];
    const float* Wc    = (const float*)d_in[8];
    const float* bc    = (const float*)d_in[9];
    float* out         = (float*)d_out;

    k_init_gemm1<<<NNODES / NPB, 256>>>(ei, x, W1);        // launch 0 (3125 blocks)
    k_pass1<<<(NEDGES + 255) / 256, 256>>>(ei, ew);        // launch 1
    k_rsqrt_bsum<<<NB, 256>>>();                           // launch 2
    k_scan<<<NB, 256>>>();                                 // launch 3
    k_fill<<<(NEDGES + 255) / 256, 256>>>(ew);             // launch 4
    k_gather<<<(NNODES * 16) / 256, 256>>>(b1);            // launch 5 (ncu slot)
    k_gemm2<<<NNODES / NPB, 256>>>(W2);                    // launch 6
    k_gather<<<(NNODES * 16) / 256, 256>>>(b2);            // launch 7
    k_pool<<<NGRAPH, 256>>>(batch, Wc, bc, out);           // launch 8
}